// round 9
// baseline (speedup 1.0000x reference)
#include <cuda_runtime.h>
#include <cuda_bf16.h>
#include <math.h>

// out[i] = z[i] * dot(pos[i], c),  c = (w_tp/(2*sqrt(3))) * W1 @ W2 @ (W3 @ ones(3))
// W1: [3,2], W2: [2,2], W3: [2,3]  row-major.
// 8 atoms/thread (8 x LDG.128 issued up-front = 3.5KB in flight per warp),
// __launch_bounds__(256,8) pins regs to 32 so occupancy stays 8 blocks/SM
// (R3's 34-reg version silently dropped to 7 blocks -> the confound).

__global__ void __launch_bounds__(256, 8)
atoms_kernel(const float4* __restrict__ pos4,
             const int4*   __restrict__ z4,
             float4*       __restrict__ out4,
             const float*  __restrict__ w_tp,
             const float*  __restrict__ W1,
             const float*  __restrict__ W2,
             const float*  __restrict__ W3,
             int n8, int n) {
    // Fold MLP into 3-vector c (uniform; L1-hit broadcasts)
    const float t30 = __ldg(&W3[0]) + __ldg(&W3[1]) + __ldg(&W3[2]);
    const float t31 = __ldg(&W3[3]) + __ldg(&W3[4]) + __ldg(&W3[5]);
    const float t20 = __ldg(&W2[0]) * t30 + __ldg(&W2[1]) * t31;
    const float t21 = __ldg(&W2[2]) * t30 + __ldg(&W2[3]) * t31;
    const float s   = __ldg(&w_tp[0]) * 0.28867513459481287f; // 1/(2*sqrt(3))
    const float c0  = (__ldg(&W1[0]) * t20 + __ldg(&W1[1]) * t21) * s;
    const float c1  = (__ldg(&W1[2]) * t20 + __ldg(&W1[3]) * t21) * s;
    const float c2  = (__ldg(&W1[4]) * t20 + __ldg(&W1[5]) * t21) * s;

    const int stride = gridDim.x * blockDim.x;
    for (int i = blockIdx.x * blockDim.x + threadIdx.x; i < n8; i += stride) {
        const int pb = 6 * i;
        const int ob = 2 * i;
        // all 8 wide loads issued before any consumer -> max MLP
        const float4 p0 = pos4[pb + 0];
        const float4 p1 = pos4[pb + 1];
        const float4 p2 = pos4[pb + 2];
        const float4 p3 = pos4[pb + 3];
        const float4 p4 = pos4[pb + 4];
        const float4 p5 = pos4[pb + 5];
        const int4   za = z4[ob + 0];
        const int4   zb = z4[ob + 1];

        float4 o0, o1;
        o0.x = (p0.x * c0 + p0.y * c1 + p0.z * c2) * (float)za.x;
        o0.y = (p0.w * c0 + p1.x * c1 + p1.y * c2) * (float)za.y;
        o0.z = (p1.z * c0 + p1.w * c1 + p2.x * c2) * (float)za.z;
        o0.w = (p2.y * c0 + p2.z * c1 + p2.w * c2) * (float)za.w;
        o1.x = (p3.x * c0 + p3.y * c1 + p3.z * c2) * (float)zb.x;
        o1.y = (p3.w * c0 + p4.x * c1 + p4.y * c2) * (float)zb.y;
        o1.z = (p4.z * c0 + p4.w * c1 + p5.x * c2) * (float)zb.z;
        o1.w = (p5.y * c0 + p5.z * c1 + p5.w * c2) * (float)zb.w;
        out4[ob + 0] = o0;
        out4[ob + 1] = o1;
    }

    // tail (n % 8 != 0) — dead for N=2M, kept for generality
    if ((n & 7) && blockIdx.x == 0 && threadIdx.x == 0) {
        const float* pos = (const float*)pos4;
        const int*   z   = (const int*)z4;
        float*       out = (float*)out4;
        for (int j = 8 * n8; j < n; j++) {
            out[j] = (pos[3 * j + 0] * c0 + pos[3 * j + 1] * c1 + pos[3 * j + 2] * c2)
                     * (float)z[j];
        }
    }
}

extern "C" void kernel_launch(void* const* d_in, const int* in_sizes, int n_in,
                              void* d_out, int out_size) {
    const float* pos  = (const float*)d_in[0];   // [N,3] f32
    const int*   z    = (const int*)d_in[1];     // [N]   i32
    const float* w_tp = (const float*)d_in[2];   // []    f32
    const float* W1   = (const float*)d_in[3];   // [3,2] f32
    const float* W2   = (const float*)d_in[4];   // [2,2] f32
    const float* W3   = (const float*)d_in[5];   // [2,3] f32
    float* out = (float*)d_out;

    const int n  = in_sizes[1];  // N atoms
    const int n8 = n >> 3;

    // Full wave of 8 blocks/SM; grid-stride handles the remainder.
    int sms = 148;
    cudaDeviceGetAttribute(&sms, cudaDevAttrMultiProcessorCount, 0);
    int blocks = 8 * sms;
    const int threads = 256;
    int needed = (n8 + threads - 1) / threads;
    if (blocks > needed) blocks = needed;
    if (blocks < 1) blocks = 1;
    atoms_kernel<<<blocks, threads>>>((const float4*)pos, (const int4*)z,
                                      (float4*)out, w_tp, W1, W2, W3, n8, n);
}

// round 12
// speedup vs baseline: 1.1394x; 1.1394x over previous
#include <cuda_runtime.h>
#include <cuda_bf16.h>
#include <math.h>

// out[i] = z[i] * dot(pos[i], c),  c = (w_tp/(2*sqrt(3))) * W1 @ W2 @ (W3 @ ones(3))
// W1: [3,2], W2: [2,2], W3: [2,3]  row-major.
//
// Warp-tile: each warp handles 128 atoms (= 96 contiguous float4 of pos).
// Global loads fully coalesced (thread t loads float4 tileBase+t, +32+t, +64+t
// -> each warp LDG.128 covers 4 full 128B lines = 4 wavefronts instead of 12
// partial-line ones). Redistribution via warp-PRIVATE smem slab, __syncwarp
// only. Stride-3 LDS.128 is bank-conflict-free.

__global__ void __launch_bounds__(256)
atoms_warptile_kernel(const float4* __restrict__ pos4,
                      const int4*   __restrict__ z4,
                      float4*       __restrict__ out4,
                      const float*  __restrict__ w_tp,
                      const float*  __restrict__ W1,
                      const float*  __restrict__ W2,
                      const float*  __restrict__ W3,
                      int n4, int n) {
    __shared__ float4 sp[8][96];            // 1.5KB per warp, 12KB per block

    // Fold MLP into 3-vector c (uniform; L1-hit broadcasts)
    const float t30 = __ldg(&W3[0]) + __ldg(&W3[1]) + __ldg(&W3[2]);
    const float t31 = __ldg(&W3[3]) + __ldg(&W3[4]) + __ldg(&W3[5]);
    const float t20 = __ldg(&W2[0]) * t30 + __ldg(&W2[1]) * t31;
    const float t21 = __ldg(&W2[2]) * t30 + __ldg(&W2[3]) * t31;
    const float s   = __ldg(&w_tp[0]) * 0.28867513459481287f; // 1/(2*sqrt(3))
    const float c0  = (__ldg(&W1[0]) * t20 + __ldg(&W1[1]) * t21) * s;
    const float c1  = (__ldg(&W1[2]) * t20 + __ldg(&W1[3]) * t21) * s;
    const float c2  = (__ldg(&W1[4]) * t20 + __ldg(&W1[5]) * t21) * s;

    const int w = threadIdx.x >> 5;          // warp in block (0..7)
    const int t = threadIdx.x & 31;          // lane
    const int wgid     = blockIdx.x * 8 + w; // global warp id
    const int numWarps = gridDim.x * 8;
    const int tiles    = (n4 + 31) >> 5;     // 32 groups (128 atoms) per warp-tile

    for (int tile = wgid; tile < tiles; tile += numWarps) {
        const int g   = (tile << 5) + t;     // this lane's 4-atom group
        const int p0  = tile * 96;           // first pos-float4 of the tile
        const int rem = 3 * n4 - p0;         // pos-float4s remaining (>0)
        const bool v  = (g < n4);

        float4 f0 = {0,0,0,0}, f1 = {0,0,0,0}, f2 = {0,0,0,0};
        int4   zz = {0,0,0,0};
        if (t < rem)      f0 = pos4[p0 + t];
        if (32 + t < rem) f1 = pos4[p0 + 32 + t];
        if (64 + t < rem) f2 = pos4[p0 + 64 + t];
        if (v)            zz = z4[g];

        __syncwarp();                        // prior iter's LDS done before overwrite
        sp[w][t]      = f0;
        sp[w][32 + t] = f1;
        sp[w][64 + t] = f2;
        __syncwarp();

        if (v) {
            const float4 a = sp[w][3 * t + 0];   // stride-3 LDS.128: conflict-free
            const float4 b = sp[w][3 * t + 1];
            const float4 d = sp[w][3 * t + 2];
            float4 o;
            o.x = (a.x * c0 + a.y * c1 + a.z * c2) * (float)zz.x;
            o.y = (a.w * c0 + b.x * c1 + b.y * c2) * (float)zz.y;
            o.z = (b.z * c0 + b.w * c1 + d.x * c2) * (float)zz.z;
            o.w = (d.y * c0 + d.z * c1 + d.w * c2) * (float)zz.w;
            out4[g] = o;                         // coalesced store
        }
    }

    // tail (n % 4 != 0) — dead for N=2M, kept for generality
    if ((n & 3) && blockIdx.x == 0 && threadIdx.x == 0) {
        const float* pos = (const float*)pos4;
        const int*   z   = (const int*)z4;
        float*       out = (float*)out4;
        for (int j = 4 * n4; j < n; j++) {
            out[j] = (pos[3 * j + 0] * c0 + pos[3 * j + 1] * c1 + pos[3 * j + 2] * c2)
                     * (float)z[j];
        }
    }
}

extern "C" void kernel_launch(void* const* d_in, const int* in_sizes, int n_in,
                              void* d_out, int out_size) {
    const float* pos  = (const float*)d_in[0];   // [N,3] f32
    const int*   z    = (const int*)d_in[1];     // [N]   i32
    const float* w_tp = (const float*)d_in[2];   // []    f32
    const float* W1   = (const float*)d_in[3];   // [3,2] f32
    const float* W2   = (const float*)d_in[4];   // [2,2] f32
    const float* W3   = (const float*)d_in[5];   // [2,3] f32
    float* out = (float*)d_out;

    const int n  = in_sizes[1];  // N atoms
    const int n4 = n >> 2;       // 4-atom groups
    const int tiles = (n4 + 31) >> 5;

    // One full wave: 8 blocks/SM x 256 threads (148 SMs on this part, as seen
    // in every profile). No host API calls here — launches only.
    int blocks = 8 * 148;
    int needed = (tiles + 7) / 8;            // 8 warps per block
    if (blocks > needed) blocks = needed;
    if (blocks < 1) blocks = 1;
    atoms_warptile_kernel<<<blocks, 256>>>((const float4*)pos, (const int4*)z,
                                           (float4*)out, w_tp, W1, W2, W3, n4, n);
}

// round 13
// speedup vs baseline: 1.1679x; 1.0250x over previous
#include <cuda_runtime.h>
#include <cuda_bf16.h>
#include <cstdint>

// out[i] = z[i] * dot(pos[i], c),  c = (w_tp/(2*sqrt(3))) * W1 @ W2 @ (W3 @ ones(3))
//
// Bulk-DMA design: pos (24MB) is pulled tile-by-tile (12KB = 1024 atoms) into
// smem via cp.async.bulk (TMA engine path -> no per-warp LSU load-issue cost,
// which the R2..R12 sweep identified as the binding cap: time ~ 1/warps,
// per-warp LDG rate constant). 2-stage mbarrier pipeline overlaps next tile's
// DMA with current compute. z via direct coalesced int4 LDG issued before the
// barrier wait; out via coalesced STG.128. Stride-3 float4 smem reads are
// bank-conflict-free.

#define NSTG   2
#define TILE_G 256                       // 4-atom groups per tile
#define TILE_POS_BYTES (TILE_G * 48)     // 12288 B

__device__ __forceinline__ unsigned su32(const void* p) {
    return (unsigned)__cvta_generic_to_shared(p);
}

__device__ __forceinline__ void mbar_wait(unsigned bar, int phase) {
    asm volatile(
        "{\n\t"
        ".reg .pred P;\n\t"
        "WL_%=:\n\t"
        "mbarrier.try_wait.parity.acquire.cta.shared::cta.b64 P, [%0], %1, 0x989680;\n\t"
        "@P bra.uni WD_%=;\n\t"
        "bra.uni WL_%=;\n\t"
        "WD_%=:\n\t"
        "}"
        :: "r"(bar), "r"((unsigned)phase) : "memory");
}

__global__ void __launch_bounds__(256, 8)
atoms_bulk_kernel(const float4* __restrict__ pos4,
                  const int4*   __restrict__ z4,
                  float4*       __restrict__ out4,
                  const float*  __restrict__ w_tp,
                  const float*  __restrict__ W1,
                  const float*  __restrict__ W2,
                  const float*  __restrict__ W3,
                  int n4, int n, int ntiles) {
    __shared__ float4 sp[NSTG][TILE_G * 3];              // 2 x 12KB
    __shared__ __align__(8) unsigned long long mbar[NSTG];

    const int t = threadIdx.x;

    if (t == 0) {
        #pragma unroll
        for (int s = 0; s < NSTG; s++)
            asm volatile("mbarrier.init.shared.b64 [%0], 1;"
                         :: "r"(su32(&mbar[s])) : "memory");
        asm volatile("fence.proxy.async.shared::cta;" ::: "memory");
    }
    __syncthreads();

    // Fold MLP into 3-vector c (uniform; L1-hit broadcasts)
    const float t30 = __ldg(&W3[0]) + __ldg(&W3[1]) + __ldg(&W3[2]);
    const float t31 = __ldg(&W3[3]) + __ldg(&W3[4]) + __ldg(&W3[5]);
    const float t20 = __ldg(&W2[0]) * t30 + __ldg(&W2[1]) * t31;
    const float t21 = __ldg(&W2[2]) * t30 + __ldg(&W2[3]) * t31;
    const float sc  = __ldg(&w_tp[0]) * 0.28867513459481287f; // 1/(2*sqrt(3))
    const float c0  = (__ldg(&W1[0]) * t20 + __ldg(&W1[1]) * t21) * sc;
    const float c1  = (__ldg(&W1[2]) * t20 + __ldg(&W1[3]) * t21) * sc;
    const float c2  = (__ldg(&W1[4]) * t20 + __ldg(&W1[5]) * t21) * sc;

    const int grid = gridDim.x;

    // prologue: DMA tile0 -> stage 0
    if (t == 0 && blockIdx.x < ntiles) {
        const int g0   = blockIdx.x * TILE_G;
        const int gcnt = min(TILE_G, n4 - g0);
        const unsigned bytes = (unsigned)gcnt * 48u;
        const unsigned bar   = su32(&mbar[0]);
        asm volatile("mbarrier.arrive.expect_tx.shared.b64 _, [%0], %1;"
                     :: "r"(bar), "r"(bytes) : "memory");
        asm volatile("cp.async.bulk.shared::cluster.global.mbarrier::complete_tx::bytes "
                     "[%0], [%1], %2, [%3];"
                     :: "r"(su32(&sp[0][0])), "l"((const void*)(pos4 + (size_t)g0 * 3)),
                        "r"(bytes), "r"(bar) : "memory");
    }

    int ph0 = 0, ph1 = 0;
    int k = 0;
    for (int tile = blockIdx.x; tile < ntiles; tile += grid, k++) {
        const int s = k & 1;

        // issue next tile's DMA into the other stage (it was consumed at
        // iteration k-1 and fenced by that iteration's __syncthreads)
        const int ntile = tile + grid;
        if (t == 0 && ntile < ntiles) {
            const int g0   = ntile * TILE_G;
            const int gcnt = min(TILE_G, n4 - g0);
            const unsigned bytes = (unsigned)gcnt * 48u;
            const unsigned bar   = su32(&mbar[s ^ 1]);
            asm volatile("mbarrier.arrive.expect_tx.shared.b64 _, [%0], %1;"
                         :: "r"(bar), "r"(bytes) : "memory");
            asm volatile("cp.async.bulk.shared::cluster.global.mbarrier::complete_tx::bytes "
                         "[%0], [%1], %2, [%3];"
                         :: "r"(su32(&sp[s ^ 1][0])), "l"((const void*)(pos4 + (size_t)g0 * 3)),
                            "r"(bytes), "r"(bar) : "memory");
        }

        // z: direct coalesced LDG, in flight while we wait for the DMA
        const int g = tile * TILE_G + t;
        const bool v = (g < n4);
        int4 zz = {0, 0, 0, 0};
        if (v) zz = z4[g];

        mbar_wait(su32(&mbar[s]), s ? ph1 : ph0);
        if (s) ph1 ^= 1; else ph0 ^= 1;

        if (v) {
            const float4 a = sp[s][3 * t + 0];   // stride-3 LDS.128: conflict-free
            const float4 b = sp[s][3 * t + 1];
            const float4 d = sp[s][3 * t + 2];
            float4 o;
            o.x = (a.x * c0 + a.y * c1 + a.z * c2) * (float)zz.x;
            o.y = (a.w * c0 + b.x * c1 + b.y * c2) * (float)zz.y;
            o.z = (b.z * c0 + b.w * c1 + d.x * c2) * (float)zz.z;
            o.w = (d.y * c0 + d.z * c1 + d.w * c2) * (float)zz.w;
            out4[g] = o;
        }
        __syncthreads();   // stage s fully consumed before it is reloaded at k+1
    }

    // tail (n % 4 != 0) — dead for N=2M, kept for generality
    if ((n & 3) && blockIdx.x == 0 && t == 0) {
        const float* pos = (const float*)pos4;
        const int*   z   = (const int*)z4;
        float*       out = (float*)out4;
        for (int j = 4 * n4; j < n; j++) {
            out[j] = (pos[3 * j + 0] * c0 + pos[3 * j + 1] * c1 + pos[3 * j + 2] * c2)
                     * (float)z[j];
        }
    }
}

extern "C" void kernel_launch(void* const* d_in, const int* in_sizes, int n_in,
                              void* d_out, int out_size) {
    const float* pos  = (const float*)d_in[0];   // [N,3] f32
    const int*   z    = (const int*)d_in[1];     // [N]   i32
    const float* w_tp = (const float*)d_in[2];   // []    f32
    const float* W1   = (const float*)d_in[3];   // [3,2] f32
    const float* W2   = (const float*)d_in[4];   // [2,2] f32
    const float* W3   = (const float*)d_in[5];   // [2,3] f32
    float* out = (float*)d_out;

    const int n      = in_sizes[1];              // N atoms
    const int n4     = n >> 2;                   // 4-atom groups
    const int ntiles = (n4 + TILE_G - 1) / TILE_G;

    int blocks = 8 * 148;                        // one full wave (148 SMs)
    if (blocks > ntiles) blocks = ntiles;
    if (blocks < 1) blocks = 1;
    atoms_bulk_kernel<<<blocks, 256>>>((const float4*)pos, (const int4*)z,
                                       (float4*)out, w_tp, W1, W2, W3,
                                       n4, n, ntiles);
}

// round 15
// speedup vs baseline: 1.2773x; 1.0938x over previous
#include <cuda_runtime.h>
#include <cuda_bf16.h>
#include <math.h>

// out[i] = z[i] * dot(pos[i], c),  c = (w_tp/(2*sqrt(3))) * W1 @ W2 @ (W3 @ ones(3))
// W1: [3,2], W2: [2,2], W3: [2,3]  row-major.
//
// Converged design (best of 12 measured variants, 8.19us, measured twice):
//  - single kernel, one full wave: 8 blocks/SM x 256 threads, grid-stride
//  - 4 atoms/thread: 3x LDG.128 pos + 1x LDG.128 z + 1x STG.128 out
//    (the warp's three 48B-strided pos LDGs touch the same 12 lines ->
//     L1 serves instrs 2-3; explicit coalescing measured slower)
//  - default cache policy (cs/cg measured neutral-or-worse)
//  - weights folded in-kernel (removes a serialized prep launch)

__global__ void __launch_bounds__(256)
atoms_kernel(const float4* __restrict__ pos4,
             const int4*   __restrict__ z4,
             float4*       __restrict__ out4,
             const float*  __restrict__ w_tp,
             const float*  __restrict__ W1,
             const float*  __restrict__ W2,
             const float*  __restrict__ W3,
             int n4, int n) {
    // Fold MLP into 3-vector c (uniform; L1-hit broadcasts)
    const float t30 = __ldg(&W3[0]) + __ldg(&W3[1]) + __ldg(&W3[2]);
    const float t31 = __ldg(&W3[3]) + __ldg(&W3[4]) + __ldg(&W3[5]);
    const float t20 = __ldg(&W2[0]) * t30 + __ldg(&W2[1]) * t31;
    const float t21 = __ldg(&W2[2]) * t30 + __ldg(&W2[3]) * t31;
    const float s   = __ldg(&w_tp[0]) * 0.28867513459481287f; // 1/(2*sqrt(3))
    const float c0  = (__ldg(&W1[0]) * t20 + __ldg(&W1[1]) * t21) * s;
    const float c1  = (__ldg(&W1[2]) * t20 + __ldg(&W1[3]) * t21) * s;
    const float c2  = (__ldg(&W1[4]) * t20 + __ldg(&W1[5]) * t21) * s;

    const int stride = gridDim.x * blockDim.x;
    for (int i = blockIdx.x * blockDim.x + threadIdx.x; i < n4; i += stride) {
        const float4 a  = pos4[3 * i + 0];
        const float4 b  = pos4[3 * i + 1];
        const float4 d  = pos4[3 * i + 2];
        const int4   zz = z4[i];
        float4 o;
        o.x = (a.x * c0 + a.y * c1 + a.z * c2) * (float)zz.x;
        o.y = (a.w * c0 + b.x * c1 + b.y * c2) * (float)zz.y;
        o.z = (b.z * c0 + b.w * c1 + d.x * c2) * (float)zz.z;
        o.w = (d.y * c0 + d.z * c1 + d.w * c2) * (float)zz.w;
        out4[i] = o;
    }

    // tail (n % 4 != 0) — dead for N=2M, kept for generality
    if ((n & 3) && blockIdx.x == 0 && threadIdx.x == 0) {
        const float* pos = (const float*)pos4;
        const int*   z   = (const int*)z4;
        float*       out = (float*)out4;
        for (int j = 4 * n4; j < n; j++) {
            out[j] = (pos[3 * j + 0] * c0 + pos[3 * j + 1] * c1 + pos[3 * j + 2] * c2)
                     * (float)z[j];
        }
    }
}

extern "C" void kernel_launch(void* const* d_in, const int* in_sizes, int n_in,
                              void* d_out, int out_size) {
    const float* pos  = (const float*)d_in[0];   // [N,3] f32
    const int*   z    = (const int*)d_in[1];     // [N]   i32
    const float* w_tp = (const float*)d_in[2];   // []    f32
    const float* W1   = (const float*)d_in[3];   // [3,2] f32
    const float* W2   = (const float*)d_in[4];   // [2,2] f32
    const float* W3   = (const float*)d_in[5];   // [2,3] f32
    float* out = (float*)d_out;

    const int n  = in_sizes[1];  // N atoms
    const int n4 = n >> 2;

    // One full wave: 8 blocks/SM x 256 threads on 148 SMs (per all profiles).
    int blocks = 8 * 148;
    const int threads = 256;
    int needed = (n4 + threads - 1) / threads;
    if (blocks > needed) blocks = needed;
    if (blocks < 1) blocks = 1;
    atoms_kernel<<<blocks, threads>>>((const float4*)pos, (const int4*)z,
                                      (float4*)out, w_tp, W1, W2, W3, n4, n);
}